// round 7
// baseline (speedup 1.0000x reference)
#include <cuda_runtime.h>
#include <cuda_bf16.h>
#include <cstdint>

#define HD   64
#define NV   16
#define TPB  128   // threads per CTA = samples per tile (M)
#define NCTA 444   // 148 SMs * 3 CTAs -> exactly one wave

// ---------------- helpers ----------------
__device__ __forceinline__ uint32_t smem_u32(const void* p) {
    uint32_t a;
    asm("{ .reg .u64 t; cvta.to.shared.u64 t, %1; cvt.u32.u64 %0, t; }" : "=r"(a) : "l"(p));
    return a;
}
__device__ __forceinline__ void ldmx4(uint32_t& r0, uint32_t& r1, uint32_t& r2, uint32_t& r3,
                                      uint32_t addr) {
    asm volatile("ldmatrix.sync.aligned.m8n8.x4.shared.b16 {%0,%1,%2,%3}, [%4];"
                 : "=r"(r0), "=r"(r1), "=r"(r2), "=r"(r3) : "r"(addr));
}
__device__ __forceinline__ void mma_bf16(float* c, const uint32_t* a,
                                         uint32_t b0, uint32_t b1) {
    asm volatile("mma.sync.aligned.m16n8k16.row.col.f32.bf16.bf16.f32 "
                 "{%0,%1,%2,%3}, {%4,%5,%6,%7}, {%8,%9}, {%0,%1,%2,%3};"
                 : "+f"(c[0]), "+f"(c[1]), "+f"(c[2]), "+f"(c[3])
                 : "r"(a[0]), "r"(a[1]), "r"(a[2]), "r"(a[3]), "r"(b0), "r"(b1));
}
__device__ __forceinline__ uint32_t split_hi_pair(float h0, float h1, float& l0, float& l1) {
    uint32_t hp;
    asm("{ .reg .b16 x, y; .reg .f32 r0, r1;\n\t"
        "cvt.rn.bf16.f32 x, %3;\n\t"
        "cvt.rn.bf16.f32 y, %4;\n\t"
        "mov.b32 %0, {x, y};\n\t"
        "cvt.f32.bf16 r0, x;\n\t"
        "cvt.f32.bf16 r1, y;\n\t"
        "sub.f32 %1, %3, r0;\n\t"
        "sub.f32 %2, %4, r1; }"
        : "=r"(hp), "=f"(l0), "=f"(l1) : "f"(h0), "f"(h1));
    return hp;
}
__device__ __forceinline__ uint32_t pack_bf16x2(float x0, float x1) {
    uint32_t r;
    asm("{ .reg .b16 x, y; cvt.rn.bf16.f32 x, %1; cvt.rn.bf16.f32 y, %2; mov.b32 %0, {x, y}; }"
        : "=r"(r) : "f"(x0), "f"(x1));
    return r;
}
__device__ __forceinline__ void cp_async16(uint32_t smem_dst, const void* gmem_src) {
    asm volatile("cp.async.cg.shared.global [%0], [%1], 16;"
                 :: "r"(smem_dst), "l"(gmem_src) : "memory");
}

// ---------------- prepared weights ----------------
struct SmallV {
    float4 l1w[32];     // {ws[2c], ws[2c+1], we[2c], we[2c+1]}
    float2 l1b[32];     // {b1[2c], b1[2c+1]}
    float2 b2w3[HD];    // {B2[j], W3[j]}
    float b3;
    float std_;
    float pad[6];
};                       // 1312 B = 82 * 16
__device__ __align__(16) SmallV g_small[NV];
// W2^T (rows j = output, cols k = input) as swizzled bf16 smem image, hi/lo splits.
// element (j,k): idx = j*64 + ((k/8 ^ (j&7))*8) + (k%8)
__device__ __align__(16) __nv_bfloat16 g_W2T[NV][2][HD * HD];

__global__ void prep_kernel(
    const float* __restrict__ stds,
    const float* __restrict__ w0_1, const float* __restrict__ b0_1,
    const float* __restrict__ w0_2, const float* __restrict__ b0_2,
    const float* __restrict__ w0_3, const float* __restrict__ b0_3,
    const float* __restrict__ W1,   const float* __restrict__ B1,
    const float* __restrict__ W2,   const float* __restrict__ B2,
    const float* __restrict__ W3,   const float* __restrict__ B3)
{
    const int v = blockIdx.x;
    const int tid = threadIdx.x;
    const float* w2 = (v == 0) ? w0_2 : W2 + (size_t)(v - 1) * HD * HD;  // [k][j]

    for (int t = tid; t < HD * HD; t += blockDim.x) {
        int k = t / HD, j = t % HD;
        float x = w2[k * HD + j];
        __nv_bfloat16 hb = __float2bfloat16_rn(x);
        float lo = x - __bfloat162float(hb);
        __nv_bfloat16 lb = __float2bfloat16_rn(lo);
        int idx = j * HD + (((k >> 3) ^ (j & 7)) << 3) + (k & 7);
        g_W2T[v][0][idx] = hb;
        g_W2T[v][1][idx] = lb;
    }
    SmallV* sv = &g_small[v];
    if (tid < 32) {
        int c = tid;
        float ws0, ws1, we0, we1, b10, b11;
        if (v == 0) {
            ws0 = ws1 = 0.0f;
            we0 = w0_1[2 * c]; we1 = w0_1[2 * c + 1];
            b10 = b0_1[2 * c]; b11 = b0_1[2 * c + 1];
        } else {
            int i = v - 1;
            ws0 = W1[(size_t)i * 2 * HD + 2 * c];
            ws1 = W1[(size_t)i * 2 * HD + 2 * c + 1];
            we0 = W1[(size_t)i * 2 * HD + HD + 2 * c];
            we1 = W1[(size_t)i * 2 * HD + HD + 2 * c + 1];
            b10 = B1[(size_t)i * HD + 2 * c];
            b11 = B1[(size_t)i * HD + 2 * c + 1];
        }
        sv->l1w[c] = make_float4(ws0, ws1, we0, we1);
        sv->l1b[c] = make_float2(b10, b11);
    }
    if (tid < HD) {
        if (v == 0) {
            sv->b2w3[tid] = make_float2(b0_2[tid], w0_3[tid]);
            if (tid == 0) { sv->b3 = b0_3[0]; sv->std_ = fabsf(stds[0]); }
        } else {
            int i = v - 1;
            sv->b2w3[tid] = make_float2(B2[(size_t)i * HD + tid], W3[(size_t)i * HD + tid]);
            if (tid == 0) { sv->b3 = B3[i]; sv->std_ = fabsf(stds[v]); }
        }
    }
}

// ---------------- per-variable kernel ----------------
// Processes one variable v for all samples. Weights staged ONCE per CTA,
// amortized over ~ntiles/gridDim tiles. Carry read from out[v-1].
__global__ __launch_bounds__(TPB, 3)
void ncm_v_kernel(const float* __restrict__ noise_v,   // noise + v*nsamp
                  const float* __restrict__ parent,    // out + (v-1)*nsamp (ignored if v==0)
                  float* __restrict__ out_v,           // out + v*nsamp
                  int nsamp, int v)
{
    __shared__ __align__(128) __nv_bfloat16 sW[2][HD * HD];  // 16 KB
    __shared__ __align__(16) SmallV sV;

    const int tid  = threadIdx.x;
    const int w    = tid >> 5;
    const int lane = tid & 31;
    const int l7   = lane & 7;
    const int l3   = lane & 3;
    const int g    = lane >> 2;  // fragment row base 0..7
    const int mi   = lane >> 3;  // ldmatrix matrix index 0..3

    // ---- stage weights once ----
    {
        const uint4* srcw = (const uint4*)&g_W2T[v][0][0];
        uint4* dstw = (uint4*)&sW[0][0];
        #pragma unroll
        for (int c = 0; c < 8; c++)
            cp_async16(smem_u32(dstw + tid + c * TPB), srcw + tid + c * TPB);
        if (tid < 82)
            cp_async16(smem_u32(((uint4*)&sV) + tid), ((const uint4*)&g_small[v]) + tid);
        asm volatile("cp.async.commit_group;" ::: "memory");
        asm volatile("cp.async.wait_group 0;" ::: "memory");
        __syncthreads();
    }

    const uint32_t sWh_b = smem_u32(&sW[0][0]);
    const uint32_t sWl_b = smem_u32(&sW[1][0]);
    const float stdv = sV.std_;
    const float b3   = sV.b3;
    const bool hasp  = (v > 0);

    const int ntiles = (nsamp + TPB - 1) / TPB;
    const int stride = gridDim.x;

    int t = blockIdx.x;
    float cr[4], er[4];
    // prologue scalar load for first tile
    if (t < ntiles) {
        int rb = t * TPB + w * 32 + g;
        #pragma unroll
        for (int q = 0; q < 4; q++) {
            int r = rb + 8 * q;
            er[q] = noise_v[r] * stdv;
            cr[q] = hasp ? parent[r] : 0.0f;
        }
    }

    while (t < ntiles) {
        const int tn = t + stride;
        // prefetch next tile's scalars (hides L2 latency behind the GEMM)
        float crn[4], ern[4];
        if (tn < ntiles) {
            int rb = tn * TPB + w * 32 + g;
            #pragma unroll
            for (int q = 0; q < 4; q++) {
                int r = rb + 8 * q;
                ern[q] = noise_v[r] * stdv;
                crn[q] = hasp ? parent[r] : 0.0f;
            }
        }

        // ---- layer 1 directly in A-fragment layout ----
        uint32_t ah[2][4][4], al[2][4][4];
        #pragma unroll
        for (int kt = 0; kt < 4; kt++) {
            float4 wA = sV.l1w[8 * kt + l3];
            float2 bA = sV.l1b[8 * kt + l3];
            float4 wB = sV.l1w[8 * kt + l3 + 4];
            float2 bB = sV.l1b[8 * kt + l3 + 4];
            #pragma unroll
            for (int q = 0; q < 4; q++) {
                const int mt = q >> 1, idx = q & 1;
                float h0 = fmaxf(fmaf(cr[q], wA.x, fmaf(er[q], wA.z, bA.x)), 0.0f);
                float h1 = fmaxf(fmaf(cr[q], wA.y, fmaf(er[q], wA.w, bA.y)), 0.0f);
                float l0, l1;
                ah[mt][kt][idx] = split_hi_pair(h0, h1, l0, l1);
                al[mt][kt][idx] = pack_bf16x2(l0, l1);
                float h2 = fmaxf(fmaf(cr[q], wB.x, fmaf(er[q], wB.z, bB.x)), 0.0f);
                float h3 = fmaxf(fmaf(cr[q], wB.y, fmaf(er[q], wB.w, bB.y)), 0.0f);
                ah[mt][kt][2 + idx] = split_hi_pair(h2, h3, l0, l1);
                al[mt][kt][2 + idx] = pack_bf16x2(l0, l1);
            }
        }

        // ---- GEMM in jt-pairs, 4 independent acc chains ----
        float p[2][2] = {{0, 0}, {0, 0}};
        #pragma unroll
        for (int jtp = 0; jtp < 4; jtp++) {
            uint32_t bh[2][8], bl[2][8];
            #pragma unroll
            for (int jt2 = 0; jt2 < 2; jt2++) {
                int jt = 2 * jtp + jt2;
                uint32_t nrowoff = (uint32_t)((jt * 8 + l7) * 128);
                uint32_t a0 = sWh_b + nrowoff + (uint32_t)(((0 + mi) ^ l7) * 16);
                uint32_t a1 = sWh_b + nrowoff + (uint32_t)(((4 + mi) ^ l7) * 16);
                ldmx4(bh[jt2][0], bh[jt2][1], bh[jt2][2], bh[jt2][3], a0);
                ldmx4(bh[jt2][4], bh[jt2][5], bh[jt2][6], bh[jt2][7], a1);
                uint32_t a2 = sWl_b + nrowoff + (uint32_t)(((0 + mi) ^ l7) * 16);
                uint32_t a3 = sWl_b + nrowoff + (uint32_t)(((4 + mi) ^ l7) * 16);
                ldmx4(bl[jt2][0], bl[jt2][1], bl[jt2][2], bl[jt2][3], a2);
                ldmx4(bl[jt2][4], bl[jt2][5], bl[jt2][6], bl[jt2][7], a3);
            }

            float acc[2][2][4];
            #pragma unroll
            for (int jt2 = 0; jt2 < 2; jt2++)
                #pragma unroll
                for (int mt = 0; mt < 2; mt++)
                    #pragma unroll
                    for (int q = 0; q < 4; q++) acc[jt2][mt][q] = 0.0f;

            #pragma unroll
            for (int kt = 0; kt < 4; kt++) {
                #pragma unroll
                for (int jt2 = 0; jt2 < 2; jt2++)
                    #pragma unroll
                    for (int mt = 0; mt < 2; mt++)
                        mma_bf16(acc[jt2][mt], ah[mt][kt], bh[jt2][2 * kt], bh[jt2][2 * kt + 1]);
                #pragma unroll
                for (int jt2 = 0; jt2 < 2; jt2++)
                    #pragma unroll
                    for (int mt = 0; mt < 2; mt++)
                        mma_bf16(acc[jt2][mt], ah[mt][kt], bl[jt2][2 * kt], bl[jt2][2 * kt + 1]);
                #pragma unroll
                for (int jt2 = 0; jt2 < 2; jt2++)
                    #pragma unroll
                    for (int mt = 0; mt < 2; mt++)
                        mma_bf16(acc[jt2][mt], al[mt][kt], bh[jt2][2 * kt], bh[jt2][2 * kt + 1]);
            }

            #pragma unroll
            for (int jt2 = 0; jt2 < 2; jt2++) {
                int j0 = (2 * jtp + jt2) * 8 + 2 * l3;
                float2 bw0 = sV.b2w3[j0];
                float2 bw1 = sV.b2w3[j0 + 1];
                #pragma unroll
                for (int mt = 0; mt < 2; mt++) {
                    p[mt][0] = fmaf(fmaxf(acc[jt2][mt][0] + bw0.x, 0.0f), bw0.y, p[mt][0]);
                    p[mt][0] = fmaf(fmaxf(acc[jt2][mt][1] + bw1.x, 0.0f), bw1.y, p[mt][0]);
                    p[mt][1] = fmaf(fmaxf(acc[jt2][mt][2] + bw0.x, 0.0f), bw0.y, p[mt][1]);
                    p[mt][1] = fmaf(fmaxf(acc[jt2][mt][3] + bw1.x, 0.0f), bw1.y, p[mt][1]);
                }
            }
        }

        // ---- reduce across quad, write 4 outputs from l3==0 lanes ----
        #pragma unroll
        for (int mt = 0; mt < 2; mt++)
            #pragma unroll
            for (int q = 0; q < 2; q++) {
                p[mt][q] += __shfl_xor_sync(0xffffffffu, p[mt][q], 1);
                p[mt][q] += __shfl_xor_sync(0xffffffffu, p[mt][q], 2);
            }
        if (l3 == 0) {
            int rb = t * TPB + w * 32 + g;   // g == lane>>2 for these lanes
            out_v[rb]      = p[0][0] + b3;
            out_v[rb + 8]  = p[0][1] + b3;
            out_v[rb + 16] = p[1][0] + b3;
            out_v[rb + 24] = p[1][1] + b3;
        }

        t = tn;
        #pragma unroll
        for (int q = 0; q < 4; q++) { cr[q] = crn[q]; er[q] = ern[q]; }
    }
}

extern "C" void kernel_launch(void* const* d_in, const int* in_sizes, int n_in,
                              void* d_out, int out_size) {
    const float* noise = (const float*)d_in[0];
    const float* stds  = (const float*)d_in[1];
    const float* w0_1  = (const float*)d_in[2];
    const float* b0_1  = (const float*)d_in[3];
    const float* w0_2  = (const float*)d_in[4];
    const float* b0_2  = (const float*)d_in[5];
    const float* w0_3  = (const float*)d_in[6];
    const float* b0_3  = (const float*)d_in[7];
    const float* W1    = (const float*)d_in[8];
    const float* B1    = (const float*)d_in[9];
    const float* W2    = (const float*)d_in[10];
    const float* B2    = (const float*)d_in[11];
    const float* W3    = (const float*)d_in[12];
    const float* B3    = (const float*)d_in[13];
    float* out = (float*)d_out;

    const int nsamp  = in_sizes[0] / NV;
    const int ntiles = (nsamp + TPB - 1) / TPB;
    const int grid   = (ntiles < NCTA) ? ntiles : NCTA;

    prep_kernel<<<NV, 256>>>(stds, w0_1, b0_1, w0_2, b0_2, w0_3, b0_3,
                             W1, B1, W2, B2, W3, B3);
    for (int v = 0; v < NV; v++) {
        const float* nv  = noise + (size_t)v * nsamp;
        const float* par = (v == 0) ? noise : out + (size_t)(v - 1) * nsamp;
        ncm_v_kernel<<<grid, TPB>>>(nv, par, out + (size_t)v * nsamp, nsamp, v);
    }
}

// round 8
// speedup vs baseline: 1.0673x; 1.0673x over previous
#include <cuda_runtime.h>
#include <cuda_bf16.h>
#include <cstdint>

#define HD    64
#define NV    16
#define TPB   128   // threads per CTA = samples per tile (M)
#define NCTA  444   // 148 SMs * 3 CTAs -> exactly one resident wave
#define NTMAX 10    // max tiles owned per CTA per chunk (4096/444 = 9.2)

// ---------------- helpers ----------------
__device__ __forceinline__ uint32_t smem_u32(const void* p) {
    uint32_t a;
    asm("{ .reg .u64 t; cvta.to.shared.u64 t, %1; cvt.u32.u64 %0, t; }" : "=r"(a) : "l"(p));
    return a;
}
__device__ __forceinline__ void ldmx4(uint32_t& r0, uint32_t& r1, uint32_t& r2, uint32_t& r3,
                                      uint32_t addr) {
    asm volatile("ldmatrix.sync.aligned.m8n8.x4.shared.b16 {%0,%1,%2,%3}, [%4];"
                 : "=r"(r0), "=r"(r1), "=r"(r2), "=r"(r3) : "r"(addr));
}
__device__ __forceinline__ void mma_bf16(float* c, const uint32_t* a,
                                         uint32_t b0, uint32_t b1) {
    asm volatile("mma.sync.aligned.m16n8k16.row.col.f32.bf16.bf16.f32 "
                 "{%0,%1,%2,%3}, {%4,%5,%6,%7}, {%8,%9}, {%0,%1,%2,%3};"
                 : "+f"(c[0]), "+f"(c[1]), "+f"(c[2]), "+f"(c[3])
                 : "r"(a[0]), "r"(a[1]), "r"(a[2]), "r"(a[3]), "r"(b0), "r"(b1));
}
__device__ __forceinline__ uint32_t split_hi_pair(float h0, float h1, float& l0, float& l1) {
    uint32_t hp;
    asm("{ .reg .b16 x, y; .reg .f32 r0, r1;\n\t"
        "cvt.rn.bf16.f32 x, %3;\n\t"
        "cvt.rn.bf16.f32 y, %4;\n\t"
        "mov.b32 %0, {x, y};\n\t"
        "cvt.f32.bf16 r0, x;\n\t"
        "cvt.f32.bf16 r1, y;\n\t"
        "sub.f32 %1, %3, r0;\n\t"
        "sub.f32 %2, %4, r1; }"
        : "=r"(hp), "=f"(l0), "=f"(l1) : "f"(h0), "f"(h1));
    return hp;
}
__device__ __forceinline__ uint32_t pack_bf16x2(float x0, float x1) {
    uint32_t r;
    asm("{ .reg .b16 x, y; cvt.rn.bf16.f32 x, %1; cvt.rn.bf16.f32 y, %2; mov.b32 %0, {x, y}; }"
        : "=r"(r) : "f"(x0), "f"(x1));
    return r;
}
__device__ __forceinline__ void cp_async16(uint32_t smem_dst, const void* gmem_src) {
    asm volatile("cp.async.cg.shared.global [%0], [%1], 16;"
                 :: "r"(smem_dst), "l"(gmem_src) : "memory");
}

// ---------------- prepared weights ----------------
struct SmallV {
    float4 l1w[32];     // {ws[2c], ws[2c+1], we[2c], we[2c+1]}
    float2 l1b[32];     // {b1[2c], b1[2c+1]}
    float2 b2w3[HD];    // {B2[j], W3[j]}
    float b3;
    float std_;
    float pad[6];
};                       // 1312 B = 82 * 16
__device__ __align__(16) SmallV g_small[NV];
// W2^T (rows j = output, cols k = input) as swizzled bf16 smem image, hi/lo splits.
__device__ __align__(16) __nv_bfloat16 g_W2T[NV][2][HD * HD];

__global__ void prep_kernel(
    const float* __restrict__ stds,
    const float* __restrict__ w0_1, const float* __restrict__ b0_1,
    const float* __restrict__ w0_2, const float* __restrict__ b0_2,
    const float* __restrict__ w0_3, const float* __restrict__ b0_3,
    const float* __restrict__ W1,   const float* __restrict__ B1,
    const float* __restrict__ W2,   const float* __restrict__ B2,
    const float* __restrict__ W3,   const float* __restrict__ B3)
{
    const int v = blockIdx.x;
    const int tid = threadIdx.x;
    const float* w2 = (v == 0) ? w0_2 : W2 + (size_t)(v - 1) * HD * HD;  // [k][j]

    for (int t = tid; t < HD * HD; t += blockDim.x) {
        int k = t / HD, j = t % HD;
        float x = w2[k * HD + j];
        __nv_bfloat16 hb = __float2bfloat16_rn(x);
        float lo = x - __bfloat162float(hb);
        __nv_bfloat16 lb = __float2bfloat16_rn(lo);
        int idx = j * HD + (((k >> 3) ^ (j & 7)) << 3) + (k & 7);
        g_W2T[v][0][idx] = hb;
        g_W2T[v][1][idx] = lb;
    }
    SmallV* sv = &g_small[v];
    if (tid < 32) {
        int c = tid;
        float ws0, ws1, we0, we1, b10, b11;
        if (v == 0) {
            ws0 = ws1 = 0.0f;
            we0 = w0_1[2 * c]; we1 = w0_1[2 * c + 1];
            b10 = b0_1[2 * c]; b11 = b0_1[2 * c + 1];
        } else {
            int i = v - 1;
            ws0 = W1[(size_t)i * 2 * HD + 2 * c];
            ws1 = W1[(size_t)i * 2 * HD + 2 * c + 1];
            we0 = W1[(size_t)i * 2 * HD + HD + 2 * c];
            we1 = W1[(size_t)i * 2 * HD + HD + 2 * c + 1];
            b10 = B1[(size_t)i * HD + 2 * c];
            b11 = B1[(size_t)i * HD + 2 * c + 1];
        }
        sv->l1w[c] = make_float4(ws0, ws1, we0, we1);
        sv->l1b[c] = make_float2(b10, b11);
    }
    if (tid < HD) {
        if (v == 0) {
            sv->b2w3[tid] = make_float2(b0_2[tid], w0_3[tid]);
            if (tid == 0) { sv->b3 = b0_3[0]; sv->std_ = fabsf(stds[0]); }
        } else {
            int i = v - 1;
            sv->b2w3[tid] = make_float2(B2[(size_t)i * HD + tid], W3[(size_t)i * HD + tid]);
            if (tid == 0) { sv->b3 = B3[i]; sv->std_ = fabsf(stds[v]); }
        }
    }
}

// ---------------- fused persistent kernel ----------------
struct __align__(128) Stage {
    __nv_bfloat16 w[2][HD * HD];   // 16 KB, W2^T hi/lo (swizzled)
    SmallV sv;                     // 1312 B
};

__global__ __launch_bounds__(TPB, 3)
void ncm_fused_kernel(const float* __restrict__ noise, float* __restrict__ out,
                      int nsamp, int ntiles)
{
    __shared__ Stage sStg[2];                 // ~34.6 KB
    __shared__ float sCar[NTMAX][TPB];        // 5 KB carry per owned tile

    const int tid  = threadIdx.x;
    const int w    = tid >> 5;
    const int lane = tid & 31;
    const int l7   = lane & 7;
    const int l3   = lane & 3;
    const int g    = lane >> 2;  // fragment row base 0..7
    const int mi   = lane >> 3;  // ldmatrix matrix index 0..3

    const int stride = gridDim.x;
    const int span   = stride * NTMAX;
    const int rowoff = w * 32 + g;            // row base within tile for this lane

    for (int cs = 0; cs < ntiles; cs += span) {
        // prologue: prefetch stage for v=0
        {
            const uint4* srcw = (const uint4*)&g_W2T[0][0][0];
            uint4* dstw = (uint4*)&sStg[0].w[0][0];
            #pragma unroll
            for (int c = 0; c < 8; c++)
                cp_async16(smem_u32(dstw + tid + c * TPB), srcw + tid + c * TPB);
            if (tid < 82)
                cp_async16(smem_u32(((uint4*)&sStg[0].sv) + tid), ((const uint4*)&g_small[0]) + tid);
            asm volatile("cp.async.commit_group;" ::: "memory");
        }

        for (int v = 0; v < NV; v++) {
            // prefetch v+1 into the other stage buffer
            if (v + 1 < NV) {
                Stage* nx = &sStg[(v + 1) & 1];
                const uint4* srcw = (const uint4*)&g_W2T[v + 1][0][0];
                uint4* dstw = (uint4*)&nx->w[0][0];
                #pragma unroll
                for (int c = 0; c < 8; c++)
                    cp_async16(smem_u32(dstw + tid + c * TPB), srcw + tid + c * TPB);
                if (tid < 82)
                    cp_async16(smem_u32(((uint4*)&nx->sv) + tid), ((const uint4*)&g_small[v + 1]) + tid);
                asm volatile("cp.async.commit_group;" ::: "memory");
                asm volatile("cp.async.wait_group 1;" ::: "memory");
            } else {
                asm volatile("cp.async.wait_group 0;" ::: "memory");
            }
            __syncthreads();   // stage v visible; prev-v readers done (barrier at loop end)

            const Stage* st = &sStg[v & 1];
            const SmallV& sv = st->sv;
            const uint32_t sWh_b = smem_u32(&st->w[0][0]);
            const uint32_t sWl_b = smem_u32(&st->w[1][0]);
            const float stdv = sv.std_;
            const float b3   = sv.b3;
            const float* noise_v = noise + (size_t)v * nsamp;
            float* out_v = out + (size_t)v * nsamp;

            // prefetch first tile's noise
            float er[4], ern[4];
            {
                int t0 = cs + blockIdx.x;
                if (t0 < ntiles) {
                    int rb = t0 * TPB + rowoff;
                    #pragma unroll
                    for (int q = 0; q < 4; q++) {
                        int r = rb + 8 * q;
                        er[q] = (r < nsamp) ? noise_v[r] * stdv : 0.0f;
                    }
                }
            }

            #pragma unroll 1
            for (int i = 0; i < NTMAX; i++) {
                const int t = cs + blockIdx.x + i * stride;
                if (t >= ntiles) break;
                const int rb = t * TPB + rowoff;

                // prefetch next tile's noise
                const int tn = t + stride;
                if (i + 1 < NTMAX && tn < ntiles) {
                    int rbn = tn * TPB + rowoff;
                    #pragma unroll
                    for (int q = 0; q < 4; q++) {
                        int r = rbn + 8 * q;
                        ern[q] = (r < nsamp) ? noise_v[r] * stdv : 0.0f;
                    }
                }

                // carry for the 4 fragment rows (warp-local smem, v=0 -> 0)
                float cr[4];
                #pragma unroll
                for (int q = 0; q < 4; q++)
                    cr[q] = (v > 0) ? sCar[i][rowoff + 8 * q] : 0.0f;

                // ---- layer 1 directly in A-fragment layout ----
                uint32_t ah[2][4][4], al[2][4][4];
                #pragma unroll
                for (int kt = 0; kt < 4; kt++) {
                    float4 wA = sv.l1w[8 * kt + l3];
                    float2 bA = sv.l1b[8 * kt + l3];
                    float4 wB = sv.l1w[8 * kt + l3 + 4];
                    float2 bB = sv.l1b[8 * kt + l3 + 4];
                    #pragma unroll
                    for (int q = 0; q < 4; q++) {
                        const int mt = q >> 1, idx = q & 1;
                        float h0 = fmaxf(fmaf(cr[q], wA.x, fmaf(er[q], wA.z, bA.x)), 0.0f);
                        float h1 = fmaxf(fmaf(cr[q], wA.y, fmaf(er[q], wA.w, bA.y)), 0.0f);
                        float l0, l1;
                        ah[mt][kt][idx] = split_hi_pair(h0, h1, l0, l1);
                        al[mt][kt][idx] = pack_bf16x2(l0, l1);
                        float h2 = fmaxf(fmaf(cr[q], wB.x, fmaf(er[q], wB.z, bB.x)), 0.0f);
                        float h3 = fmaxf(fmaf(cr[q], wB.y, fmaf(er[q], wB.w, bB.y)), 0.0f);
                        ah[mt][kt][2 + idx] = split_hi_pair(h2, h3, l0, l1);
                        al[mt][kt][2 + idx] = pack_bf16x2(l0, l1);
                    }
                }

                // ---- GEMM in jt-pairs, 4 independent acc chains ----
                float p[2][2] = {{0, 0}, {0, 0}};
                #pragma unroll
                for (int jtp = 0; jtp < 4; jtp++) {
                    uint32_t bh[2][8], bl[2][8];
                    #pragma unroll
                    for (int jt2 = 0; jt2 < 2; jt2++) {
                        int jt = 2 * jtp + jt2;
                        uint32_t nrowoff = (uint32_t)((jt * 8 + l7) * 128);
                        uint32_t a0 = sWh_b + nrowoff + (uint32_t)(((0 + mi) ^ l7) * 16);
                        uint32_t a1 = sWh_b + nrowoff + (uint32_t)(((4 + mi) ^ l7) * 16);
                        ldmx4(bh[jt2][0], bh[jt2][1], bh[jt2][2], bh[jt2][3], a0);
                        ldmx4(bh[jt2][4], bh[jt2][5], bh[jt2][6], bh[jt2][7], a1);
                        uint32_t a2 = sWl_b + nrowoff + (uint32_t)(((0 + mi) ^ l7) * 16);
                        uint32_t a3 = sWl_b + nrowoff + (uint32_t)(((4 + mi) ^ l7) * 16);
                        ldmx4(bl[jt2][0], bl[jt2][1], bl[jt2][2], bl[jt2][3], a2);
                        ldmx4(bl[jt2][4], bl[jt2][5], bl[jt2][6], bl[jt2][7], a3);
                    }

                    float acc[2][2][4];
                    #pragma unroll
                    for (int jt2 = 0; jt2 < 2; jt2++)
                        #pragma unroll
                        for (int mt = 0; mt < 2; mt++)
                            #pragma unroll
                            for (int q = 0; q < 4; q++) acc[jt2][mt][q] = 0.0f;

                    #pragma unroll
                    for (int kt = 0; kt < 4; kt++) {
                        #pragma unroll
                        for (int jt2 = 0; jt2 < 2; jt2++)
                            #pragma unroll
                            for (int mt = 0; mt < 2; mt++)
                                mma_bf16(acc[jt2][mt], ah[mt][kt], bh[jt2][2 * kt], bh[jt2][2 * kt + 1]);
                        #pragma unroll
                        for (int jt2 = 0; jt2 < 2; jt2++)
                            #pragma unroll
                            for (int mt = 0; mt < 2; mt++)
                                mma_bf16(acc[jt2][mt], ah[mt][kt], bl[jt2][2 * kt], bl[jt2][2 * kt + 1]);
                        #pragma unroll
                        for (int jt2 = 0; jt2 < 2; jt2++)
                            #pragma unroll
                            for (int mt = 0; mt < 2; mt++)
                                mma_bf16(acc[jt2][mt], al[mt][kt], bh[jt2][2 * kt], bh[jt2][2 * kt + 1]);
                    }

                    #pragma unroll
                    for (int jt2 = 0; jt2 < 2; jt2++) {
                        int j0 = (2 * jtp + jt2) * 8 + 2 * l3;
                        float2 bw0 = sv.b2w3[j0];
                        float2 bw1 = sv.b2w3[j0 + 1];
                        #pragma unroll
                        for (int mt = 0; mt < 2; mt++) {
                            p[mt][0] = fmaf(fmaxf(acc[jt2][mt][0] + bw0.x, 0.0f), bw0.y, p[mt][0]);
                            p[mt][0] = fmaf(fmaxf(acc[jt2][mt][1] + bw1.x, 0.0f), bw1.y, p[mt][0]);
                            p[mt][1] = fmaf(fmaxf(acc[jt2][mt][2] + bw0.x, 0.0f), bw0.y, p[mt][1]);
                            p[mt][1] = fmaf(fmaxf(acc[jt2][mt][3] + bw1.x, 0.0f), bw1.y, p[mt][1]);
                        }
                    }
                }

                // ---- reduce across quad; l3==0 lanes hold rows g, g+8, g+16, g+24 ----
                #pragma unroll
                for (int mt = 0; mt < 2; mt++)
                    #pragma unroll
                    for (int q = 0; q < 2; q++) {
                        p[mt][q] += __shfl_xor_sync(0xffffffffu, p[mt][q], 1);
                        p[mt][q] += __shfl_xor_sync(0xffffffffu, p[mt][q], 2);
                    }
                if (l3 == 0) {
                    float v0 = p[0][0] + b3, v1 = p[0][1] + b3;
                    float v2 = p[1][0] + b3, v3 = p[1][1] + b3;
                    int base = w * 32 + g;       // g == lane>>2 here
                    sCar[i][base]      = v0;
                    sCar[i][base + 8]  = v1;
                    sCar[i][base + 16] = v2;
                    sCar[i][base + 24] = v3;
                    int rbw = t * TPB + base;
                    if (rbw      < nsamp) out_v[rbw]      = v0;
                    if (rbw + 8  < nsamp) out_v[rbw + 8]  = v1;
                    if (rbw + 16 < nsamp) out_v[rbw + 16] = v2;
                    if (rbw + 24 < nsamp) out_v[rbw + 24] = v3;
                }
                __syncwarp();

                #pragma unroll
                for (int q = 0; q < 4; q++) er[q] = ern[q];
            }

            __syncthreads();   // all warps done with stage v before overwrite
        }
    }
}

extern "C" void kernel_launch(void* const* d_in, const int* in_sizes, int n_in,
                              void* d_out, int out_size) {
    const float* noise = (const float*)d_in[0];
    const float* stds  = (const float*)d_in[1];
    const float* w0_1  = (const float*)d_in[2];
    const float* b0_1  = (const float*)d_in[3];
    const float* w0_2  = (const float*)d_in[4];
    const float* b0_2  = (const float*)d_in[5];
    const float* w0_3  = (const float*)d_in[6];
    const float* b0_3  = (const float*)d_in[7];
    const float* W1    = (const float*)d_in[8];
    const float* B1    = (const float*)d_in[9];
    const float* W2    = (const float*)d_in[10];
    const float* B2    = (const float*)d_in[11];
    const float* W3    = (const float*)d_in[12];
    const float* B3    = (const float*)d_in[13];
    float* out = (float*)d_out;

    const int nsamp  = in_sizes[0] / NV;
    const int ntiles = (nsamp + TPB - 1) / TPB;
    const int grid   = (ntiles < NCTA) ? ntiles : NCTA;

    prep_kernel<<<NV, 256>>>(stds, w0_1, b0_1, w0_2, b0_2, w0_3, b0_3,
                             W1, B1, W2, B2, W3, B3);
    ncm_fused_kernel<<<grid, TPB>>>(noise, out, nsamp, ntiles);
}

// round 9
// speedup vs baseline: 1.5217x; 1.4256x over previous
#include <cuda_runtime.h>
#include <cuda_fp16.h>
#include <cstdint>

#define HD    64
#define NV    16
#define TPB   128   // threads per CTA = samples per tile (M)
#define NCTA  444   // 148 SMs * 3 CTAs -> one resident wave
#define NTMAX 10    // max tiles owned per CTA per chunk

// ---------------- helpers ----------------
__device__ __forceinline__ uint32_t smem_u32(const void* p) {
    uint32_t a;
    asm("{ .reg .u64 t; cvta.to.shared.u64 t, %1; cvt.u32.u64 %0, t; }" : "=r"(a) : "l"(p));
    return a;
}
__device__ __forceinline__ void ldmx4(uint32_t& r0, uint32_t& r1, uint32_t& r2, uint32_t& r3,
                                      uint32_t addr) {
    asm volatile("ldmatrix.sync.aligned.m8n8.x4.shared.b16 {%0,%1,%2,%3}, [%4];"
                 : "=r"(r0), "=r"(r1), "=r"(r2), "=r"(r3) : "r"(addr));
}
__device__ __forceinline__ void mma_f16(float* c, const uint32_t* a,
                                        uint32_t b0, uint32_t b1) {
    asm volatile("mma.sync.aligned.m16n8k16.row.col.f32.f16.f16.f32 "
                 "{%0,%1,%2,%3}, {%4,%5,%6,%7}, {%8,%9}, {%0,%1,%2,%3};"
                 : "+f"(c[0]), "+f"(c[1]), "+f"(c[2]), "+f"(c[3])
                 : "r"(a[0]), "r"(a[1]), "r"(a[2]), "r"(a[3]), "r"(b0), "r"(b1));
}
__device__ __forceinline__ uint32_t pack_f16x2(float x0, float x1) {
    uint32_t r;
    asm("{ .reg .b16 x, y; cvt.rn.f16.f32 x, %1; cvt.rn.f16.f32 y, %2; mov.b32 %0, {x, y}; }"
        : "=r"(r) : "f"(x0), "f"(x1));
    return r;
}
__device__ __forceinline__ void cp_async16(uint32_t smem_dst, const void* gmem_src) {
    asm volatile("cp.async.cg.shared.global [%0], [%1], 16;"
                 :: "r"(smem_dst), "l"(gmem_src) : "memory");
}

// ---------------- prepared weights ----------------
struct SmallV {
    float4 l1w[32];     // {ws[2c], ws[2c+1], we[2c], we[2c+1]}
    float2 l1b[32];     // {b1[2c], b1[2c+1]}
    float2 b2w3[HD];    // {B2[j], W3[j]}
    float b3;
    float std_;
    float pad[6];
};                       // 1312 B = 82 * 16
__device__ __align__(16) SmallV g_small[NV];
// W2^T (rows j = output, cols k = input) as swizzled fp16 smem image, hi/lo splits.
__device__ __align__(16) __half g_W2T[NV][2][HD * HD];

__global__ void prep_kernel(
    const float* __restrict__ stds,
    const float* __restrict__ w0_1, const float* __restrict__ b0_1,
    const float* __restrict__ w0_2, const float* __restrict__ b0_2,
    const float* __restrict__ w0_3, const float* __restrict__ b0_3,
    const float* __restrict__ W1,   const float* __restrict__ B1,
    const float* __restrict__ W2,   const float* __restrict__ B2,
    const float* __restrict__ W3,   const float* __restrict__ B3)
{
    const int v = blockIdx.x;
    const int tid = threadIdx.x;
    const float* w2 = (v == 0) ? w0_2 : W2 + (size_t)(v - 1) * HD * HD;  // [k][j]

    for (int t = tid; t < HD * HD; t += blockDim.x) {
        int k = t / HD, j = t % HD;
        float x = w2[k * HD + j];
        __half hb = __float2half_rn(x);
        float lo = x - __half2float(hb);
        __half lb = __float2half_rn(lo);
        int idx = j * HD + (((k >> 3) ^ (j & 7)) << 3) + (k & 7);
        g_W2T[v][0][idx] = hb;
        g_W2T[v][1][idx] = lb;
    }
    SmallV* sv = &g_small[v];
    if (tid < 32) {
        int c = tid;
        float ws0, ws1, we0, we1, b10, b11;
        if (v == 0) {
            ws0 = ws1 = 0.0f;
            we0 = w0_1[2 * c]; we1 = w0_1[2 * c + 1];
            b10 = b0_1[2 * c]; b11 = b0_1[2 * c + 1];
        } else {
            int i = v - 1;
            ws0 = W1[(size_t)i * 2 * HD + 2 * c];
            ws1 = W1[(size_t)i * 2 * HD + 2 * c + 1];
            we0 = W1[(size_t)i * 2 * HD + HD + 2 * c];
            we1 = W1[(size_t)i * 2 * HD + HD + 2 * c + 1];
            b10 = B1[(size_t)i * HD + 2 * c];
            b11 = B1[(size_t)i * HD + 2 * c + 1];
        }
        sv->l1w[c] = make_float4(ws0, ws1, we0, we1);
        sv->l1b[c] = make_float2(b10, b11);
    }
    if (tid < HD) {
        if (v == 0) {
            sv->b2w3[tid] = make_float2(b0_2[tid], w0_3[tid]);
            if (tid == 0) { sv->b3 = b0_3[0]; sv->std_ = fabsf(stds[0]); }
        } else {
            int i = v - 1;
            sv->b2w3[tid] = make_float2(B2[(size_t)i * HD + tid], W3[(size_t)i * HD + tid]);
            if (tid == 0) { sv->b3 = B3[i]; sv->std_ = fabsf(stds[v]); }
        }
    }
}

// ---------------- fused persistent kernel ----------------
struct __align__(128) Stage {
    __half w[2][HD * HD];   // 16 KB, W2^T hi/lo (swizzled)
    SmallV sv;              // 1312 B
};

__global__ __launch_bounds__(TPB, 3)
void ncm_fused_kernel(const float* __restrict__ noise, float* __restrict__ out,
                      int nsamp, int ntiles)
{
    __shared__ Stage sStg[2];                 // ~34.6 KB
    __shared__ float sCar[NTMAX][TPB];        // 5 KB carry per owned tile

    const int tid  = threadIdx.x;
    const int w    = tid >> 5;
    const int lane = tid & 31;
    const int l7   = lane & 7;
    const int l3   = lane & 3;
    const int g    = lane >> 2;  // fragment row base 0..7
    const int mi   = lane >> 3;  // ldmatrix matrix index 0..3

    const int stride = gridDim.x;
    const int span   = stride * NTMAX;
    const int rowoff = w * 32 + g;            // row base within tile for this lane

    for (int cs = 0; cs < ntiles; cs += span) {
        // prologue: prefetch stage for v=0
        {
            const uint4* srcw = (const uint4*)&g_W2T[0][0][0];
            uint4* dstw = (uint4*)&sStg[0].w[0][0];
            #pragma unroll
            for (int c = 0; c < 8; c++)
                cp_async16(smem_u32(dstw + tid + c * TPB), srcw + tid + c * TPB);
            if (tid < 82)
                cp_async16(smem_u32(((uint4*)&sStg[0].sv) + tid), ((const uint4*)&g_small[0]) + tid);
            asm volatile("cp.async.commit_group;" ::: "memory");
        }

        for (int v = 0; v < NV; v++) {
            // prefetch v+1 into the other stage buffer
            if (v + 1 < NV) {
                Stage* nx = &sStg[(v + 1) & 1];
                const uint4* srcw = (const uint4*)&g_W2T[v + 1][0][0];
                uint4* dstw = (uint4*)&nx->w[0][0];
                #pragma unroll
                for (int c = 0; c < 8; c++)
                    cp_async16(smem_u32(dstw + tid + c * TPB), srcw + tid + c * TPB);
                if (tid < 82)
                    cp_async16(smem_u32(((uint4*)&nx->sv) + tid), ((const uint4*)&g_small[v + 1]) + tid);
                asm volatile("cp.async.commit_group;" ::: "memory");
                asm volatile("cp.async.wait_group 1;" ::: "memory");
            } else {
                asm volatile("cp.async.wait_group 0;" ::: "memory");
            }
            __syncthreads();   // stage v visible; prev-v readers done

            const Stage* st = &sStg[v & 1];
            const SmallV& sv = st->sv;
            const uint32_t sWh_b = smem_u32(&st->w[0][0]);
            const uint32_t sWl_b = smem_u32(&st->w[1][0]);
            const float stdv = sv.std_;
            const float b3   = sv.b3;
            const float* noise_v = noise + (size_t)v * nsamp;
            float* out_v = out + (size_t)v * nsamp;

            // prefetch first tile's noise
            float er[4], ern[4];
            {
                int t0 = cs + blockIdx.x;
                if (t0 < ntiles) {
                    int rb = t0 * TPB + rowoff;
                    #pragma unroll
                    for (int q = 0; q < 4; q++) {
                        int r = rb + 8 * q;
                        er[q] = (r < nsamp) ? noise_v[r] * stdv : 0.0f;
                    }
                }
            }

            #pragma unroll 1
            for (int i = 0; i < NTMAX; i++) {
                const int t = cs + blockIdx.x + i * stride;
                if (t >= ntiles) break;

                // prefetch next tile's noise
                const int tn = t + stride;
                if (i + 1 < NTMAX && tn < ntiles) {
                    int rbn = tn * TPB + rowoff;
                    #pragma unroll
                    for (int q = 0; q < 4; q++) {
                        int r = rbn + 8 * q;
                        ern[q] = (r < nsamp) ? noise_v[r] * stdv : 0.0f;
                    }
                }

                // carry for the 4 fragment rows (warp-local smem, v=0 -> 0)
                float cr[4];
                #pragma unroll
                for (int q = 0; q < 4; q++)
                    cr[q] = (v > 0) ? sCar[i][rowoff + 8 * q] : 0.0f;

                // ---- layer 1 directly in A-fragment layout (fp16, single limb) ----
                uint32_t ah[2][4][4];
                #pragma unroll
                for (int kt = 0; kt < 4; kt++) {
                    float4 wA = sv.l1w[8 * kt + l3];
                    float2 bA = sv.l1b[8 * kt + l3];
                    float4 wB = sv.l1w[8 * kt + l3 + 4];
                    float2 bB = sv.l1b[8 * kt + l3 + 4];
                    #pragma unroll
                    for (int q = 0; q < 4; q++) {
                        const int mt = q >> 1, idx = q & 1;
                        float h0 = fmaxf(fmaf(cr[q], wA.x, fmaf(er[q], wA.z, bA.x)), 0.0f);
                        float h1 = fmaxf(fmaf(cr[q], wA.y, fmaf(er[q], wA.w, bA.y)), 0.0f);
                        ah[mt][kt][idx] = pack_f16x2(h0, h1);
                        float h2 = fmaxf(fmaf(cr[q], wB.x, fmaf(er[q], wB.z, bB.x)), 0.0f);
                        float h3 = fmaxf(fmaf(cr[q], wB.y, fmaf(er[q], wB.w, bB.y)), 0.0f);
                        ah[mt][kt][2 + idx] = pack_f16x2(h2, h3);
                    }
                }

                // ---- GEMM in jt-pairs: D = A*Bhi + A*Blo, 4 indep acc chains ----
                float p[2][2] = {{0, 0}, {0, 0}};
                #pragma unroll
                for (int jtp = 0; jtp < 4; jtp++) {
                    uint32_t bh[2][8], bl[2][8];
                    #pragma unroll
                    for (int jt2 = 0; jt2 < 2; jt2++) {
                        int jt = 2 * jtp + jt2;
                        uint32_t nrowoff = (uint32_t)((jt * 8 + l7) * 128);
                        uint32_t a0 = sWh_b + nrowoff + (uint32_t)(((0 + mi) ^ l7) * 16);
                        uint32_t a1 = sWh_b + nrowoff + (uint32_t)(((4 + mi) ^ l7) * 16);
                        ldmx4(bh[jt2][0], bh[jt2][1], bh[jt2][2], bh[jt2][3], a0);
                        ldmx4(bh[jt2][4], bh[jt2][5], bh[jt2][6], bh[jt2][7], a1);
                        uint32_t a2 = sWl_b + nrowoff + (uint32_t)(((0 + mi) ^ l7) * 16);
                        uint32_t a3 = sWl_b + nrowoff + (uint32_t)(((4 + mi) ^ l7) * 16);
                        ldmx4(bl[jt2][0], bl[jt2][1], bl[jt2][2], bl[jt2][3], a2);
                        ldmx4(bl[jt2][4], bl[jt2][5], bl[jt2][6], bl[jt2][7], a3);
                    }

                    float acc[2][2][4];
                    #pragma unroll
                    for (int jt2 = 0; jt2 < 2; jt2++)
                        #pragma unroll
                        for (int mt = 0; mt < 2; mt++)
                            #pragma unroll
                            for (int q = 0; q < 4; q++) acc[jt2][mt][q] = 0.0f;

                    #pragma unroll
                    for (int kt = 0; kt < 4; kt++) {
                        #pragma unroll
                        for (int jt2 = 0; jt2 < 2; jt2++)
                            #pragma unroll
                            for (int mt = 0; mt < 2; mt++)
                                mma_f16(acc[jt2][mt], ah[mt][kt], bh[jt2][2 * kt], bh[jt2][2 * kt + 1]);
                        #pragma unroll
                        for (int jt2 = 0; jt2 < 2; jt2++)
                            #pragma unroll
                            for (int mt = 0; mt < 2; mt++)
                                mma_f16(acc[jt2][mt], ah[mt][kt], bl[jt2][2 * kt], bl[jt2][2 * kt + 1]);
                    }

                    #pragma unroll
                    for (int jt2 = 0; jt2 < 2; jt2++) {
                        int j0 = (2 * jtp + jt2) * 8 + 2 * l3;
                        float2 bw0 = sv.b2w3[j0];
                        float2 bw1 = sv.b2w3[j0 + 1];
                        #pragma unroll
                        for (int mt = 0; mt < 2; mt++) {
                            p[mt][0] = fmaf(fmaxf(acc[jt2][mt][0] + bw0.x, 0.0f), bw0.y, p[mt][0]);
                            p[mt][0] = fmaf(fmaxf(acc[jt2][mt][1] + bw1.x, 0.0f), bw1.y, p[mt][0]);
                            p[mt][1] = fmaf(fmaxf(acc[jt2][mt][2] + bw0.x, 0.0f), bw0.y, p[mt][1]);
                            p[mt][1] = fmaf(fmaxf(acc[jt2][mt][3] + bw1.x, 0.0f), bw1.y, p[mt][1]);
                        }
                    }
                }

                // ---- reduce across quad; l3==0 lanes hold rows g, g+8, g+16, g+24 ----
                #pragma unroll
                for (int mt = 0; mt < 2; mt++)
                    #pragma unroll
                    for (int q = 0; q < 2; q++) {
                        p[mt][q] += __shfl_xor_sync(0xffffffffu, p[mt][q], 1);
                        p[mt][q] += __shfl_xor_sync(0xffffffffu, p[mt][q], 2);
                    }
                if (l3 == 0) {
                    float v0 = p[0][0] + b3, v1 = p[0][1] + b3;
                    float v2 = p[1][0] + b3, v3 = p[1][1] + b3;
                    int base = w * 32 + g;
                    sCar[i][base]      = v0;
                    sCar[i][base + 8]  = v1;
                    sCar[i][base + 16] = v2;
                    sCar[i][base + 24] = v3;
                    int rbw = t * TPB + base;
                    if (rbw      < nsamp) out_v[rbw]      = v0;
                    if (rbw + 8  < nsamp) out_v[rbw + 8]  = v1;
                    if (rbw + 16 < nsamp) out_v[rbw + 16] = v2;
                    if (rbw + 24 < nsamp) out_v[rbw + 24] = v3;
                }
                __syncwarp();

                #pragma unroll
                for (int q = 0; q < 4; q++) er[q] = ern[q];
            }

            __syncthreads();   // all warps done with stage v before overwrite
        }
    }
}

extern "C" void kernel_launch(void* const* d_in, const int* in_sizes, int n_in,
                              void* d_out, int out_size) {
    const float* noise = (const float*)d_in[0];
    const float* stds  = (const float*)d_in[1];
    const float* w0_1  = (const float*)d_in[2];
    const float* b0_1  = (const float*)d_in[3];
    const float* w0_2  = (const float*)d_in[4];
    const float* b0_2  = (const float*)d_in[5];
    const float* w0_3  = (const float*)d_in[6];
    const float* b0_3  = (const float*)d_in[7];
    const float* W1    = (const float*)d_in[8];
    const float* B1    = (const float*)d_in[9];
    const float* W2    = (const float*)d_in[10];
    const float* B2    = (const float*)d_in[11];
    const float* W3    = (const float*)d_in[12];
    const float* B3    = (const float*)d_in[13];
    float* out = (float*)d_out;

    const int nsamp  = in_sizes[0] / NV;
    const int ntiles = (nsamp + TPB - 1) / TPB;
    const int grid   = (ntiles < NCTA) ? ntiles : NCTA;

    prep_kernel<<<NV, 256>>>(stds, w0_1, b0_1, w0_2, b0_2, w0_3, b0_3,
                             W1, B1, W2, B2, W3, B3);
    ncm_fused_kernel<<<grid, TPB>>>(noise, out, nsamp, ntiles);
}

// round 10
// speedup vs baseline: 2.3161x; 1.5221x over previous
#include <cuda_runtime.h>
#include <cuda_fp16.h>
#include <cstdint>

#define HD    64
#define NV    16
#define TPB   128   // threads per CTA = samples per tile (M)
#define NCTA  444   // 148 SMs * 3 CTAs -> one resident wave
#define NTMAX 10    // max tiles owned per CTA per chunk

// ---------------- helpers ----------------
__device__ __forceinline__ uint32_t smem_u32(const void* p) {
    uint32_t a;
    asm("{ .reg .u64 t; cvta.to.shared.u64 t, %1; cvt.u32.u64 %0, t; }" : "=r"(a) : "l"(p));
    return a;
}
__device__ __forceinline__ void ldmx4(uint32_t& r0, uint32_t& r1, uint32_t& r2, uint32_t& r3,
                                      uint32_t addr) {
    asm volatile("ldmatrix.sync.aligned.m8n8.x4.shared.b16 {%0,%1,%2,%3}, [%4];"
                 : "=r"(r0), "=r"(r1), "=r"(r2), "=r"(r3) : "r"(addr));
}
__device__ __forceinline__ void mma_f16(float* c, const uint32_t* a,
                                        uint32_t b0, uint32_t b1) {
    asm volatile("mma.sync.aligned.m16n8k16.row.col.f32.f16.f16.f32 "
                 "{%0,%1,%2,%3}, {%4,%5,%6,%7}, {%8,%9}, {%0,%1,%2,%3};"
                 : "+f"(c[0]), "+f"(c[1]), "+f"(c[2]), "+f"(c[3])
                 : "r"(a[0]), "r"(a[1]), "r"(a[2]), "r"(a[3]), "r"(b0), "r"(b1));
}
__device__ __forceinline__ uint32_t pack_f16x2(float x0, float x1) {
    uint32_t r;
    asm("{ .reg .b16 x, y; cvt.rn.f16.f32 x, %1; cvt.rn.f16.f32 y, %2; mov.b32 %0, {x, y}; }"
        : "=r"(r) : "f"(x0), "f"(x1));
    return r;
}
__device__ __forceinline__ void cp_async16(uint32_t smem_dst, const void* gmem_src) {
    asm volatile("cp.async.cg.shared.global [%0], [%1], 16;"
                 :: "r"(smem_dst), "l"(gmem_src) : "memory");
}

// ---------------- prepared weights ----------------
struct SmallV {
    float4 l1w[32];     // {ws[2c], ws[2c+1], we[2c], we[2c+1]}
    float2 l1b[32];     // {b1[2c], b1[2c+1]}
    float2 b2w3[HD];    // {B2[j], W3[j]}
    float b3;
    float std_;
    float pad[6];
};                       // 1312 B = 82 * 16
__device__ __align__(16) SmallV g_small[NV];
// W2^T (rows j = output, cols k = input) as swizzled fp16 smem image (single limb).
__device__ __align__(16) __half g_W2T[NV][HD * HD];

__global__ void prep_kernel(
    const float* __restrict__ stds,
    const float* __restrict__ w0_1, const float* __restrict__ b0_1,
    const float* __restrict__ w0_2, const float* __restrict__ b0_2,
    const float* __restrict__ w0_3, const float* __restrict__ b0_3,
    const float* __restrict__ W1,   const float* __restrict__ B1,
    const float* __restrict__ W2,   const float* __restrict__ B2,
    const float* __restrict__ W3,   const float* __restrict__ B3)
{
    const int v = blockIdx.x;
    const int tid = threadIdx.x;
    const float* w2 = (v == 0) ? w0_2 : W2 + (size_t)(v - 1) * HD * HD;  // [k][j]

    for (int t = tid; t < HD * HD; t += blockDim.x) {
        int k = t / HD, j = t % HD;
        float x = w2[k * HD + j];
        int idx = j * HD + (((k >> 3) ^ (j & 7)) << 3) + (k & 7);
        g_W2T[v][idx] = __float2half_rn(x);
    }
    SmallV* sv = &g_small[v];
    if (tid < 32) {
        int c = tid;
        float ws0, ws1, we0, we1, b10, b11;
        if (v == 0) {
            ws0 = ws1 = 0.0f;
            we0 = w0_1[2 * c]; we1 = w0_1[2 * c + 1];
            b10 = b0_1[2 * c]; b11 = b0_1[2 * c + 1];
        } else {
            int i = v - 1;
            ws0 = W1[(size_t)i * 2 * HD + 2 * c];
            ws1 = W1[(size_t)i * 2 * HD + 2 * c + 1];
            we0 = W1[(size_t)i * 2 * HD + HD + 2 * c];
            we1 = W1[(size_t)i * 2 * HD + HD + 2 * c + 1];
            b10 = B1[(size_t)i * HD + 2 * c];
            b11 = B1[(size_t)i * HD + 2 * c + 1];
        }
        sv->l1w[c] = make_float4(ws0, ws1, we0, we1);
        sv->l1b[c] = make_float2(b10, b11);
    }
    if (tid < HD) {
        if (v == 0) {
            sv->b2w3[tid] = make_float2(b0_2[tid], w0_3[tid]);
            if (tid == 0) { sv->b3 = b0_3[0]; sv->std_ = fabsf(stds[0]); }
        } else {
            int i = v - 1;
            sv->b2w3[tid] = make_float2(B2[(size_t)i * HD + tid], W3[(size_t)i * HD + tid]);
            if (tid == 0) { sv->b3 = B3[i]; sv->std_ = fabsf(stds[v]); }
        }
    }
}

// ---------------- fused persistent kernel ----------------
struct __align__(128) Stage {
    __half w[HD * HD];   // 8 KB, W2^T (swizzled fp16)
    SmallV sv;           // 1312 B
};

__global__ __launch_bounds__(TPB, 3)
void ncm_fused_kernel(const float* __restrict__ noise, float* __restrict__ out,
                      int nsamp, int ntiles)
{
    __shared__ Stage sStg[2];                 // ~18.6 KB
    __shared__ float sCar[NTMAX][TPB];        // 5 KB carry per owned tile

    const int tid  = threadIdx.x;
    const int w    = tid >> 5;
    const int lane = tid & 31;
    const int l7   = lane & 7;
    const int l3   = lane & 3;
    const int g    = lane >> 2;  // fragment row base 0..7
    const int mi   = lane >> 3;  // ldmatrix matrix index 0..3

    const int stride = gridDim.x;
    const int span   = stride * NTMAX;
    const int rowoff = w * 32 + g;            // row base within tile for this lane

    for (int cs = 0; cs < ntiles; cs += span) {
        // prologue: prefetch stage for v=0
        {
            const uint4* srcw = (const uint4*)&g_W2T[0][0];
            uint4* dstw = (uint4*)&sStg[0].w[0];
            #pragma unroll
            for (int c = 0; c < 4; c++)
                cp_async16(smem_u32(dstw + tid + c * TPB), srcw + tid + c * TPB);
            if (tid < 82)
                cp_async16(smem_u32(((uint4*)&sStg[0].sv) + tid), ((const uint4*)&g_small[0]) + tid);
            asm volatile("cp.async.commit_group;" ::: "memory");
        }

        for (int v = 0; v < NV; v++) {
            // prefetch v+1 into the other stage buffer
            if (v + 1 < NV) {
                Stage* nx = &sStg[(v + 1) & 1];
                const uint4* srcw = (const uint4*)&g_W2T[v + 1][0];
                uint4* dstw = (uint4*)&nx->w[0];
                #pragma unroll
                for (int c = 0; c < 4; c++)
                    cp_async16(smem_u32(dstw + tid + c * TPB), srcw + tid + c * TPB);
                if (tid < 82)
                    cp_async16(smem_u32(((uint4*)&nx->sv) + tid), ((const uint4*)&g_small[v + 1]) + tid);
                asm volatile("cp.async.commit_group;" ::: "memory");
                asm volatile("cp.async.wait_group 1;" ::: "memory");
            } else {
                asm volatile("cp.async.wait_group 0;" ::: "memory");
            }
            __syncthreads();   // stage v visible; prev-v readers done

            const Stage* st = &sStg[v & 1];
            const SmallV& sv = st->sv;
            const uint32_t sWh_b = smem_u32(&st->w[0]);
            const float stdv = sv.std_;
            const float b3   = sv.b3;
            const float* noise_v = noise + (size_t)v * nsamp;
            float* out_v = out + (size_t)v * nsamp;

            // ---- load ALL B fragments for this variable (tile-invariant) ----
            uint32_t bh[4][2][8];
            #pragma unroll
            for (int jtp = 0; jtp < 4; jtp++)
                #pragma unroll
                for (int jt2 = 0; jt2 < 2; jt2++) {
                    int jt = 2 * jtp + jt2;
                    uint32_t nrowoff = (uint32_t)((jt * 8 + l7) * 128);
                    uint32_t a0 = sWh_b + nrowoff + (uint32_t)(((0 + mi) ^ l7) * 16);
                    uint32_t a1 = sWh_b + nrowoff + (uint32_t)(((4 + mi) ^ l7) * 16);
                    ldmx4(bh[jtp][jt2][0], bh[jtp][jt2][1], bh[jtp][jt2][2], bh[jtp][jt2][3], a0);
                    ldmx4(bh[jtp][jt2][4], bh[jtp][jt2][5], bh[jtp][jt2][6], bh[jtp][jt2][7], a1);
                }

            // prefetch first tile's noise
            float er[4], ern[4];
            {
                int t0 = cs + blockIdx.x;
                if (t0 < ntiles) {
                    int rb = t0 * TPB + rowoff;
                    #pragma unroll
                    for (int q = 0; q < 4; q++) {
                        int r = rb + 8 * q;
                        er[q] = (r < nsamp) ? noise_v[r] * stdv : 0.0f;
                    }
                }
            }

            #pragma unroll 1
            for (int i = 0; i < NTMAX; i++) {
                const int t = cs + blockIdx.x + i * stride;
                if (t >= ntiles) break;

                // prefetch next tile's noise
                const int tn = t + stride;
                if (i + 1 < NTMAX && tn < ntiles) {
                    int rbn = tn * TPB + rowoff;
                    #pragma unroll
                    for (int q = 0; q < 4; q++) {
                        int r = rbn + 8 * q;
                        ern[q] = (r < nsamp) ? noise_v[r] * stdv : 0.0f;
                    }
                }

                // carry for the 4 fragment rows (warp-local smem, v=0 -> 0)
                float cr[4];
                #pragma unroll
                for (int q = 0; q < 4; q++)
                    cr[q] = (v > 0) ? sCar[i][rowoff + 8 * q] : 0.0f;

                // ---- layer 1 directly in A-fragment layout (fp16) ----
                uint32_t ah[2][4][4];
                #pragma unroll
                for (int kt = 0; kt < 4; kt++) {
                    float4 wA = sv.l1w[8 * kt + l3];
                    float2 bA = sv.l1b[8 * kt + l3];
                    float4 wB = sv.l1w[8 * kt + l3 + 4];
                    float2 bB = sv.l1b[8 * kt + l3 + 4];
                    #pragma unroll
                    for (int q = 0; q < 4; q++) {
                        const int mt = q >> 1, idx = q & 1;
                        float h0 = fmaxf(fmaf(cr[q], wA.x, fmaf(er[q], wA.z, bA.x)), 0.0f);
                        float h1 = fmaxf(fmaf(cr[q], wA.y, fmaf(er[q], wA.w, bA.y)), 0.0f);
                        ah[mt][kt][idx] = pack_f16x2(h0, h1);
                        float h2 = fmaxf(fmaf(cr[q], wB.x, fmaf(er[q], wB.z, bB.x)), 0.0f);
                        float h3 = fmaxf(fmaf(cr[q], wB.y, fmaf(er[q], wB.w, bB.y)), 0.0f);
                        ah[mt][kt][2 + idx] = pack_f16x2(h2, h3);
                    }
                }

                // ---- GEMM: D = A*B, register-resident B, 4 indep acc chains ----
                float p[2][2] = {{0, 0}, {0, 0}};
                #pragma unroll
                for (int jtp = 0; jtp < 4; jtp++) {
                    float acc[2][2][4];
                    #pragma unroll
                    for (int jt2 = 0; jt2 < 2; jt2++)
                        #pragma unroll
                        for (int mt = 0; mt < 2; mt++)
                            #pragma unroll
                            for (int q = 0; q < 4; q++) acc[jt2][mt][q] = 0.0f;

                    #pragma unroll
                    for (int kt = 0; kt < 4; kt++)
                        #pragma unroll
                        for (int jt2 = 0; jt2 < 2; jt2++)
                            #pragma unroll
                            for (int mt = 0; mt < 2; mt++)
                                mma_f16(acc[jt2][mt], ah[mt][kt],
                                        bh[jtp][jt2][2 * kt], bh[jtp][jt2][2 * kt + 1]);

                    #pragma unroll
                    for (int jt2 = 0; jt2 < 2; jt2++) {
                        int j0 = (2 * jtp + jt2) * 8 + 2 * l3;
                        float2 bw0 = sv.b2w3[j0];
                        float2 bw1 = sv.b2w3[j0 + 1];
                        #pragma unroll
                        for (int mt = 0; mt < 2; mt++) {
                            p[mt][0] = fmaf(fmaxf(acc[jt2][mt][0] + bw0.x, 0.0f), bw0.y, p[mt][0]);
                            p[mt][0] = fmaf(fmaxf(acc[jt2][mt][1] + bw1.x, 0.0f), bw1.y, p[mt][0]);
                            p[mt][1] = fmaf(fmaxf(acc[jt2][mt][2] + bw0.x, 0.0f), bw0.y, p[mt][1]);
                            p[mt][1] = fmaf(fmaxf(acc[jt2][mt][3] + bw1.x, 0.0f), bw1.y, p[mt][1]);
                        }
                    }
                }

                // ---- reduce across quad; l3==0 lanes hold rows g, g+8, g+16, g+24 ----
                #pragma unroll
                for (int mt = 0; mt < 2; mt++)
                    #pragma unroll
                    for (int q = 0; q < 2; q++) {
                        p[mt][q] += __shfl_xor_sync(0xffffffffu, p[mt][q], 1);
                        p[mt][q] += __shfl_xor_sync(0xffffffffu, p[mt][q], 2);
                    }
                if (l3 == 0) {
                    float v0 = p[0][0] + b3, v1 = p[0][1] + b3;
                    float v2 = p[1][0] + b3, v3 = p[1][1] + b3;
                    int base = w * 32 + g;
                    sCar[i][base]      = v0;
                    sCar[i][base + 8]  = v1;
                    sCar[i][base + 16] = v2;
                    sCar[i][base + 24] = v3;
                    int rbw = t * TPB + base;
                    if (rbw      < nsamp) out_v[rbw]      = v0;
                    if (rbw + 8  < nsamp) out_v[rbw + 8]  = v1;
                    if (rbw + 16 < nsamp) out_v[rbw + 16] = v2;
                    if (rbw + 24 < nsamp) out_v[rbw + 24] = v3;
                }
                __syncwarp();

                #pragma unroll
                for (int q = 0; q < 4; q++) er[q] = ern[q];
            }

            __syncthreads();   // all warps done with stage v before overwrite
        }
    }
}

extern "C" void kernel_launch(void* const* d_in, const int* in_sizes, int n_in,
                              void* d_out, int out_size) {
    const float* noise = (const float*)d_in[0];
    const float* stds  = (const float*)d_in[1];
    const float* w0_1  = (const float*)d_in[2];
    const float* b0_1  = (const float*)d_in[3];
    const float* w0_2  = (const float*)d_in[4];
    const float* b0_2  = (const float*)d_in[5];
    const float* w0_3  = (const float*)d_in[6];
    const float* b0_3  = (const float*)d_in[7];
    const float* W1    = (const float*)d_in[8];
    const float* B1    = (const float*)d_in[9];
    const float* W2    = (const float*)d_in[10];
    const float* B2    = (const float*)d_in[11];
    const float* W3    = (const float*)d_in[12];
    const float* B3    = (const float*)d_in[13];
    float* out = (float*)d_out;

    const int nsamp  = in_sizes[0] / NV;
    const int ntiles = (nsamp + TPB - 1) / TPB;
    const int grid   = (ntiles < NCTA) ? ntiles : NCTA;

    prep_kernel<<<NV, 256>>>(stds, w0_1, b0_1, w0_2, b0_2, w0_3, b0_3,
                             W1, B1, W2, B2, W3, B3);
    ncm_fused_kernel<<<grid, TPB>>>(noise, out, nsamp, ntiles);
}

// round 11
// speedup vs baseline: 2.3846x; 1.0296x over previous
#include <cuda_runtime.h>
#include <cuda_fp16.h>
#include <cstdint>

#define HD    64
#define NV    16
#define TPB   128   // threads per CTA = samples per tile (M)
#define NCTA  444   // 148 SMs * 3 CTAs -> one resident wave
#define NTMAX 10    // max tiles owned per CTA per chunk

typedef unsigned long long u64;

// ---------------- helpers ----------------
__device__ __forceinline__ uint32_t smem_u32(const void* p) {
    uint32_t a;
    asm("{ .reg .u64 t; cvta.to.shared.u64 t, %1; cvt.u32.u64 %0, t; }" : "=r"(a) : "l"(p));
    return a;
}
__device__ __forceinline__ void ldmx4(uint32_t& r0, uint32_t& r1, uint32_t& r2, uint32_t& r3,
                                      uint32_t addr) {
    asm volatile("ldmatrix.sync.aligned.m8n8.x4.shared.b16 {%0,%1,%2,%3}, [%4];"
                 : "=r"(r0), "=r"(r1), "=r"(r2), "=r"(r3) : "r"(addr));
}
__device__ __forceinline__ void mma_f16(float* c, const uint32_t* a,
                                        uint32_t b0, uint32_t b1) {
    asm volatile("mma.sync.aligned.m16n8k16.row.col.f32.f16.f16.f32 "
                 "{%0,%1,%2,%3}, {%4,%5,%6,%7}, {%8,%9}, {%0,%1,%2,%3};"
                 : "+f"(c[0]), "+f"(c[1]), "+f"(c[2]), "+f"(c[3])
                 : "r"(a[0]), "r"(a[1]), "r"(a[2]), "r"(a[3]), "r"(b0), "r"(b1));
}
// packed f32x2 fma (sm_100): lanewise IEEE fma
__device__ __forceinline__ u64 fma2(u64 a, u64 b, u64 c) {
    u64 d;
    asm("fma.rn.f32x2 %0, %1, %2, %3;" : "=l"(d) : "l"(a), "l"(b), "l"(c));
    return d;
}
__device__ __forceinline__ u64 dup2(float x) {
    u64 d;
    asm("mov.b64 %0, {%1, %1};" : "=l"(d) : "f"(x));
    return d;
}
// unpack f32x2 pair, convert to f16x2 with fused relu: lo lane -> lo half
__device__ __forceinline__ uint32_t cvt_relu_pack(u64 h) {
    uint32_t r;
    asm("{ .reg .f32 lo, hi; mov.b64 {lo, hi}, %1; cvt.rn.relu.f16x2.f32 %0, hi, lo; }"
        : "=r"(r) : "l"(h));
    return r;
}
__device__ __forceinline__ void cp_async16(uint32_t smem_dst, const void* gmem_src) {
    asm volatile("cp.async.cg.shared.global [%0], [%1], 16;"
                 :: "r"(smem_dst), "l"(gmem_src) : "memory");
}

// ---------------- prepared weights ----------------
struct SmallV {
    float4 l1w[32];     // {ws[2c], ws[2c+1], we[2c], we[2c+1]}
    float2 l1b[32];     // {b1[2c], b1[2c+1]}
    float2 b2w3[HD];    // {B2[j], W3[j]}
    float b3;
    float std_;
    float pad[6];
};                       // 1312 B = 82 * 16
__device__ __align__(16) SmallV g_small[NV];
// W2^T (rows j = output, cols k = input) as swizzled fp16 smem image.
__device__ __align__(16) __half g_W2T[NV][HD * HD];

__global__ void prep_kernel(
    const float* __restrict__ stds,
    const float* __restrict__ w0_1, const float* __restrict__ b0_1,
    const float* __restrict__ w0_2, const float* __restrict__ b0_2,
    const float* __restrict__ w0_3, const float* __restrict__ b0_3,
    const float* __restrict__ W1,   const float* __restrict__ B1,
    const float* __restrict__ W2,   const float* __restrict__ B2,
    const float* __restrict__ W3,   const float* __restrict__ B3)
{
    const int v = blockIdx.x;
    const int tid = threadIdx.x;
    const float* w2 = (v == 0) ? w0_2 : W2 + (size_t)(v - 1) * HD * HD;  // [k][j]

    for (int t = tid; t < HD * HD; t += blockDim.x) {
        int k = t / HD, j = t % HD;
        float x = w2[k * HD + j];
        int idx = j * HD + (((k >> 3) ^ (j & 7)) << 3) + (k & 7);
        g_W2T[v][idx] = __float2half_rn(x);
    }
    SmallV* sv = &g_small[v];
    if (tid < 32) {
        int c = tid;
        float ws0, ws1, we0, we1, b10, b11;
        if (v == 0) {
            ws0 = ws1 = 0.0f;
            we0 = w0_1[2 * c]; we1 = w0_1[2 * c + 1];
            b10 = b0_1[2 * c]; b11 = b0_1[2 * c + 1];
        } else {
            int i = v - 1;
            ws0 = W1[(size_t)i * 2 * HD + 2 * c];
            ws1 = W1[(size_t)i * 2 * HD + 2 * c + 1];
            we0 = W1[(size_t)i * 2 * HD + HD + 2 * c];
            we1 = W1[(size_t)i * 2 * HD + HD + 2 * c + 1];
            b10 = B1[(size_t)i * HD + 2 * c];
            b11 = B1[(size_t)i * HD + 2 * c + 1];
        }
        sv->l1w[c] = make_float4(ws0, ws1, we0, we1);
        sv->l1b[c] = make_float2(b10, b11);
    }
    if (tid < HD) {
        if (v == 0) {
            sv->b2w3[tid] = make_float2(b0_2[tid], w0_3[tid]);
            if (tid == 0) { sv->b3 = b0_3[0]; sv->std_ = fabsf(stds[0]); }
        } else {
            int i = v - 1;
            sv->b2w3[tid] = make_float2(B2[(size_t)i * HD + tid], W3[(size_t)i * HD + tid]);
            if (tid == 0) { sv->b3 = B3[i]; sv->std_ = fabsf(stds[v]); }
        }
    }
}

// ---------------- fused persistent kernel ----------------
struct __align__(128) Stage {
    __half w[HD * HD];   // 8 KB, W2^T (swizzled fp16)
    SmallV sv;           // 1312 B
};

__global__ __launch_bounds__(TPB, 3)
void ncm_fused_kernel(const float* __restrict__ noise, float* __restrict__ out,
                      int nsamp, int ntiles)
{
    __shared__ Stage sStg[2];                 // ~18.6 KB
    __shared__ float sCar[NTMAX][TPB];        // 5 KB carry per owned tile

    const int tid  = threadIdx.x;
    const int w    = tid >> 5;
    const int lane = tid & 31;
    const int l7   = lane & 7;
    const int l3   = lane & 3;
    const int g    = lane >> 2;  // fragment row base 0..7
    const int mi   = lane >> 3;  // ldmatrix matrix index 0..3

    const int stride = gridDim.x;
    const int span   = stride * NTMAX;
    const int rowoff = w * 32 + g;            // row base within tile for this lane

    for (int cs = 0; cs < ntiles; cs += span) {
        // prologue: prefetch stage for v=0
        {
            const uint4* srcw = (const uint4*)&g_W2T[0][0];
            uint4* dstw = (uint4*)&sStg[0].w[0];
            #pragma unroll
            for (int c = 0; c < 4; c++)
                cp_async16(smem_u32(dstw + tid + c * TPB), srcw + tid + c * TPB);
            if (tid < 82)
                cp_async16(smem_u32(((uint4*)&sStg[0].sv) + tid), ((const uint4*)&g_small[0]) + tid);
            asm volatile("cp.async.commit_group;" ::: "memory");
        }

        for (int v = 0; v < NV; v++) {
            // prefetch v+1 into the other stage buffer
            if (v + 1 < NV) {
                Stage* nx = &sStg[(v + 1) & 1];
                const uint4* srcw = (const uint4*)&g_W2T[v + 1][0];
                uint4* dstw = (uint4*)&nx->w[0];
                #pragma unroll
                for (int c = 0; c < 4; c++)
                    cp_async16(smem_u32(dstw + tid + c * TPB), srcw + tid + c * TPB);
                if (tid < 82)
                    cp_async16(smem_u32(((uint4*)&nx->sv) + tid), ((const uint4*)&g_small[v + 1]) + tid);
                asm volatile("cp.async.commit_group;" ::: "memory");
                asm volatile("cp.async.wait_group 1;" ::: "memory");
            } else {
                asm volatile("cp.async.wait_group 0;" ::: "memory");
            }
            __syncthreads();   // stage v visible; prev-v readers done

            const Stage* st = &sStg[v & 1];
            const SmallV& sv = st->sv;
            const uint32_t sWh_b = smem_u32(&st->w[0]);
            const float stdv = sv.std_;
            const float b3   = sv.b3;
            const float* noise_v = noise + (size_t)v * nsamp;
            float* out_v = out + (size_t)v * nsamp;

            // ---- load ALL B fragments for this variable (tile-invariant) ----
            uint32_t bh[4][2][8];
            #pragma unroll
            for (int jtp = 0; jtp < 4; jtp++)
                #pragma unroll
                for (int jt2 = 0; jt2 < 2; jt2++) {
                    int jt = 2 * jtp + jt2;
                    uint32_t nrowoff = (uint32_t)((jt * 8 + l7) * 128);
                    uint32_t a0 = sWh_b + nrowoff + (uint32_t)(((0 + mi) ^ l7) * 16);
                    uint32_t a1 = sWh_b + nrowoff + (uint32_t)(((4 + mi) ^ l7) * 16);
                    ldmx4(bh[jtp][jt2][0], bh[jtp][jt2][1], bh[jtp][jt2][2], bh[jtp][jt2][3], a0);
                    ldmx4(bh[jtp][jt2][4], bh[jtp][jt2][5], bh[jtp][jt2][6], bh[jtp][jt2][7], a1);
                }

            // prefetch first tile's noise
            float er[4], ern[4];
            {
                int t0 = cs + blockIdx.x;
                if (t0 < ntiles) {
                    int rb = t0 * TPB + rowoff;
                    #pragma unroll
                    for (int q = 0; q < 4; q++) {
                        int r = rb + 8 * q;
                        er[q] = (r < nsamp) ? noise_v[r] * stdv : 0.0f;
                    }
                }
            }

            #pragma unroll 1
            for (int i = 0; i < NTMAX; i++) {
                const int t = cs + blockIdx.x + i * stride;
                if (t >= ntiles) break;

                // prefetch next tile's noise
                const int tn = t + stride;
                if (i + 1 < NTMAX && tn < ntiles) {
                    int rbn = tn * TPB + rowoff;
                    #pragma unroll
                    for (int q = 0; q < 4; q++) {
                        int r = rbn + 8 * q;
                        ern[q] = (r < nsamp) ? noise_v[r] * stdv : 0.0f;
                    }
                }

                // carry for the 4 fragment rows (warp-local smem, v=0 -> 0)
                u64 crd[4], erd[4];
                #pragma unroll
                for (int q = 0; q < 4; q++) {
                    float c = (v > 0) ? sCar[i][rowoff + 8 * q] : 0.0f;
                    crd[q] = dup2(c);
                    erd[q] = dup2(er[q]);
                }

                // ---- layer 1: packed f32x2 FMA + fused relu/pack to f16x2 ----
                uint32_t ah[2][4][4];
                #pragma unroll
                for (int kt = 0; kt < 4; kt++) {
                    ulonglong2 wAp = *(const ulonglong2*)&sv.l1w[8 * kt + l3];      // {ws01, we01}
                    u64       bAp = *(const u64*)&sv.l1b[8 * kt + l3];
                    ulonglong2 wBp = *(const ulonglong2*)&sv.l1w[8 * kt + l3 + 4];
                    u64       bBp = *(const u64*)&sv.l1b[8 * kt + l3 + 4];
                    #pragma unroll
                    for (int q = 0; q < 4; q++) {
                        const int mt = q >> 1, idx = q & 1;
                        u64 hA = fma2(crd[q], wAp.x, fma2(erd[q], wAp.y, bAp));
                        ah[mt][kt][idx] = cvt_relu_pack(hA);
                        u64 hB = fma2(crd[q], wBp.x, fma2(erd[q], wBp.y, bBp));
                        ah[mt][kt][2 + idx] = cvt_relu_pack(hB);
                    }
                }

                // ---- GEMM: D = B2 + A*B (bias folded into acc init) ----
                float p[2][2] = {{0, 0}, {0, 0}};
                #pragma unroll
                for (int jtp = 0; jtp < 4; jtp++) {
                    float2 bw0[2], bw1[2];
                    #pragma unroll
                    for (int jt2 = 0; jt2 < 2; jt2++) {
                        int j0 = (2 * jtp + jt2) * 8 + 2 * l3;
                        bw0[jt2] = sv.b2w3[j0];
                        bw1[jt2] = sv.b2w3[j0 + 1];
                    }

                    float acc[2][2][4];
                    #pragma unroll
                    for (int jt2 = 0; jt2 < 2; jt2++)
                        #pragma unroll
                        for (int mt = 0; mt < 2; mt++) {
                            acc[jt2][mt][0] = bw0[jt2].x;
                            acc[jt2][mt][1] = bw1[jt2].x;
                            acc[jt2][mt][2] = bw0[jt2].x;
                            acc[jt2][mt][3] = bw1[jt2].x;
                        }

                    #pragma unroll
                    for (int kt = 0; kt < 4; kt++)
                        #pragma unroll
                        for (int jt2 = 0; jt2 < 2; jt2++)
                            #pragma unroll
                            for (int mt = 0; mt < 2; mt++)
                                mma_f16(acc[jt2][mt], ah[mt][kt],
                                        bh[jtp][jt2][2 * kt], bh[jtp][jt2][2 * kt + 1]);

                    #pragma unroll
                    for (int jt2 = 0; jt2 < 2; jt2++)
                        #pragma unroll
                        for (int mt = 0; mt < 2; mt++) {
                            p[mt][0] = fmaf(fmaxf(acc[jt2][mt][0], 0.0f), bw0[jt2].y, p[mt][0]);
                            p[mt][0] = fmaf(fmaxf(acc[jt2][mt][1], 0.0f), bw1[jt2].y, p[mt][0]);
                            p[mt][1] = fmaf(fmaxf(acc[jt2][mt][2], 0.0f), bw0[jt2].y, p[mt][1]);
                            p[mt][1] = fmaf(fmaxf(acc[jt2][mt][3], 0.0f), bw1[jt2].y, p[mt][1]);
                        }
                }

                // ---- reduce across quad; l3==0 lanes hold rows g, g+8, g+16, g+24 ----
                #pragma unroll
                for (int mt = 0; mt < 2; mt++)
                    #pragma unroll
                    for (int q = 0; q < 2; q++) {
                        p[mt][q] += __shfl_xor_sync(0xffffffffu, p[mt][q], 1);
                        p[mt][q] += __shfl_xor_sync(0xffffffffu, p[mt][q], 2);
                    }
                if (l3 == 0) {
                    float v0 = p[0][0] + b3, v1 = p[0][1] + b3;
                    float v2 = p[1][0] + b3, v3 = p[1][1] + b3;
                    int base = w * 32 + g;
                    sCar[i][base]      = v0;
                    sCar[i][base + 8]  = v1;
                    sCar[i][base + 16] = v2;
                    sCar[i][base + 24] = v3;
                    int rbw = t * TPB + base;
                    if (rbw      < nsamp) out_v[rbw]      = v0;
                    if (rbw + 8  < nsamp) out_v[rbw + 8]  = v1;
                    if (rbw + 16 < nsamp) out_v[rbw + 16] = v2;
                    if (rbw + 24 < nsamp) out_v[rbw + 24] = v3;
                }
                __syncwarp();

                #pragma unroll
                for (int q = 0; q < 4; q++) er[q] = ern[q];
            }

            __syncthreads();   // all warps done with stage v before overwrite
        }
    }
}

extern "C" void kernel_launch(void* const* d_in, const int* in_sizes, int n_in,
                              void* d_out, int out_size) {
    const float* noise = (const float*)d_in[0];
    const float* stds  = (const float*)d_in[1];
    const float* w0_1  = (const float*)d_in[2];
    const float* b0_1  = (const float*)d_in[3];
    const float* w0_2  = (const float*)d_in[4];
    const float* b0_2  = (const float*)d_in[5];
    const float* w0_3  = (const float*)d_in[6];
    const float* b0_3  = (const float*)d_in[7];
    const float* W1    = (const float*)d_in[8];
    const float* B1    = (const float*)d_in[9];
    const float* W2    = (const float*)d_in[10];
    const float* B2    = (const float*)d_in[11];
    const float* W3    = (const float*)d_in[12];
    const float* B3    = (const float*)d_in[13];
    float* out = (float*)d_out;

    const int nsamp  = in_sizes[0] / NV;
    const int ntiles = (nsamp + TPB - 1) / TPB;
    const int grid   = (ntiles < NCTA) ? ntiles : NCTA;

    prep_kernel<<<NV, 256>>>(stds, w0_1, b0_1, w0_2, b0_2, w0_3, b0_3,
                             W1, B1, W2, B2, W3, B3);
    ncm_fused_kernel<<<grid, TPB>>>(noise, out, nsamp, ntiles);
}